// round 2
// baseline (speedup 1.0000x reference)
#include <cuda_runtime.h>
#include <cuda_bf16.h>

#define D 64
#define D4 (D / 4)          // 16 float4 per row
#define NODES_MAX 100000

// Scratch (static device globals: allocation-free, allowed by harness rules)
__device__ float  g_deg[NODES_MAX];
__device__ float  g_dis[NODES_MAX];
__device__ float4 g_h[NODES_MAX * D4];   // h = x@K (+ id contribution), 25.6 MB

// Vector atomic add with scalar fallback
__device__ __forceinline__ void atom_add_f4(float4* addr, float4 v) {
#if defined(__CUDA_ARCH__) && (__CUDA_ARCH__ >= 900)
    atomicAdd(addr, v);
#else
    float* p = reinterpret_cast<float*>(addr);
    atomicAdd(p + 0, v.x);
    atomicAdd(p + 1, v.y);
    atomicAdd(p + 2, v.z);
    atomicAdd(p + 3, v.w);
#endif
}

// ---------------------------------------------------------------------------
// 1) deg init: self-loop weight 1.0
__global__ void k_deg_init(int n_nodes) {
    int i = blockIdx.x * blockDim.x + threadIdx.x;
    if (i < n_nodes) g_deg[i] = 1.0f;
}

// 2) deg accumulate over edges (segment_sum by row)
__global__ void __launch_bounds__(256) k_deg_acc(const int* __restrict__ row,
                          const float* __restrict__ w, int n_edges) {
    int e = blockIdx.x * blockDim.x + threadIdx.x;
    if (e < n_edges) atomicAdd(&g_deg[row[e]], w[e]);
}

// 3) dis = rsqrt(deg)   (deg >= 1 always, no zero guard needed)
__global__ void k_dis(int n_nodes) {
    int i = blockIdx.x * blockDim.x + threadIdx.x;
    if (i < n_nodes) g_dis[i] = rsqrtf(g_deg[i]);
}

// 4) h = x @ K.   4 rows per block, 256 threads; K staged in smem.
__global__ void k_gemm(const float* __restrict__ x,
                       const float* __restrict__ K, int n_nodes) {
    __shared__ float sK[D][D];
    int tid = threadIdx.x;
    for (int i = tid; i < D * D; i += 256) sK[i >> 6][i & 63] = K[i];
    __syncthreads();
    int r   = tid >> 6;          // 0..3
    int j   = tid & 63;          // output column
    int row = blockIdx.x * 4 + r;
    if (row < n_nodes) {
        const float* xr = x + row * D;
        float acc = 0.0f;
#pragma unroll
        for (int k = 0; k < D; k++) acc += __ldg(&xr[k]) * sK[k][j];
        reinterpret_cast<float*>(g_h)[row * D + j] = acc;
    }
}

// 5) h[id_index[t]] += x[id_index[t]] @ K_id  (atomic: id_index may repeat)
__global__ void k_gemm_id(const float* __restrict__ x,
                          const float* __restrict__ Kid,
                          const int* __restrict__ id_index, int n_id) {
    __shared__ float sK[D][D];
    int tid = threadIdx.x;
    for (int i = tid; i < D * D; i += 256) sK[i >> 6][i & 63] = Kid[i];
    __syncthreads();
    int r = tid >> 6;
    int j = tid & 63;
    int t = blockIdx.x * 4 + r;
    if (t < n_id) {
        int node = __ldg(&id_index[t]);
        const float* xr = x + node * D;
        float acc = 0.0f;
#pragma unroll
        for (int k = 0; k < D; k++) acc += __ldg(&xr[k]) * sK[k][j];
        atomicAdd(&reinterpret_cast<float*>(g_h)[node * D + j], acc);
    }
}

// 6) out init: bias + self-loop contribution  out[i] = bias + dis[i]^2 * h[i]
__global__ void k_out_init(float4* __restrict__ out,
                           const float* __restrict__ bias, int n_nodes) {
    int t = blockIdx.x * blockDim.x + threadIdx.x;
    if (t < n_nodes * D4) {
        int node = t >> 4;
        int l    = t & 15;
        float s  = g_dis[node];
        s = s * s;
        float4 hv = g_h[t];
        float4 b  = reinterpret_cast<const float4*>(bias)[l];
        out[t] = make_float4(b.x + s * hv.x, b.y + s * hv.y,
                             b.z + s * hv.z, b.w + s * hv.w);
    }
}

// 7) SpMM: 16 lanes per edge, float4 gather + float4 vector atomicAdd
__global__ void __launch_bounds__(256) k_spmm(const int* __restrict__ row,
                       const int* __restrict__ col,
                       const float* __restrict__ w,
                       float4* __restrict__ out, int n_edges) {
    int t = blockIdx.x * blockDim.x + threadIdx.x;
    int e = t >> 4;
    int l = t & 15;
    if (e < n_edges) {
        int r = __ldg(&row[e]);
        int c = __ldg(&col[e]);
        float wn = __ldg(&g_dis[r]) * __ldg(&w[e]) * __ldg(&g_dis[c]);
        float4 v = g_h[c * D4 + l];
        v.x *= wn; v.y *= wn; v.z *= wn; v.w *= wn;
        atom_add_f4(&out[r * D4 + l], v);
    }
}

extern "C" void kernel_launch(void* const* d_in, const int* in_sizes, int n_in,
                              void* d_out, int out_size) {
    const float* x        = (const float*)d_in[0];
    const int*   ei       = (const int*)d_in[1];
    const int*   id_index = (const int*)d_in[2];
    const float* ew       = (const float*)d_in[3];
    const float* K        = (const float*)d_in[4];
    const float* Kid      = (const float*)d_in[5];
    const float* bias     = (const float*)d_in[6];
    float*       out      = (float*)d_out;

    int n_nodes = in_sizes[0] / D;
    int n_edges = in_sizes[1] / 2;
    int n_id    = in_sizes[2];

    const int* row = ei;
    const int* colp = ei + n_edges;

    k_deg_init<<<(n_nodes + 255) / 256, 256>>>(n_nodes);
    k_deg_acc<<<(n_edges + 255) / 256, 256>>>(row, ew, n_edges);
    k_dis<<<(n_nodes + 255) / 256, 256>>>(n_nodes);
    k_gemm<<<(n_nodes + 3) / 4, 256>>>(x, K, n_nodes);
    k_gemm_id<<<(n_id + 3) / 4, 256>>>(x, Kid, id_index, n_id);
    k_out_init<<<(n_nodes * D4 + 255) / 256, 256>>>((float4*)out, bias, n_nodes);
    k_spmm<<<((long long)n_edges * 16 + 255) / 256, 256>>>(row, colp, ew,
                                                           (float4*)out, n_edges);
}

// round 3
// speedup vs baseline: 1.1158x; 1.1158x over previous
#include <cuda_runtime.h>
#include <cuda_bf16.h>

#define D 64
#define D4 (D / 4)          // 16 float4 per row
#define NODES_MAX 100000
#define GR 32               // gemm rows per block

// Scratch (static device globals: allocation-free, allowed by harness rules)
__device__ float  g_deg[NODES_MAX];
__device__ float  g_dis[NODES_MAX];
__device__ float4 g_h[NODES_MAX * D4];   // h = x@K (+ id contribution), 25.6 MB

// Vector atomic add with scalar fallback
__device__ __forceinline__ void atom_add_f4(float4* addr, float4 v) {
#if defined(__CUDA_ARCH__) && (__CUDA_ARCH__ >= 900)
    atomicAdd(addr, v);
#else
    float* p = reinterpret_cast<float*>(addr);
    atomicAdd(p + 0, v.x);
    atomicAdd(p + 1, v.y);
    atomicAdd(p + 2, v.z);
    atomicAdd(p + 3, v.w);
#endif
}

// ---------------------------------------------------------------------------
// 1) deg init: self-loop weight 1.0
__global__ void k_deg_init(int n_nodes) {
    int i = blockIdx.x * blockDim.x + threadIdx.x;
    if (i < n_nodes) g_deg[i] = 1.0f;
}

// 2) deg accumulate over edges (segment_sum by row)
__global__ void __launch_bounds__(256) k_deg_acc(const int* __restrict__ row,
                          const float* __restrict__ w, int n_edges) {
    int e = blockIdx.x * blockDim.x + threadIdx.x;
    if (e < n_edges) atomicAdd(&g_deg[row[e]], w[e]);
}

// 3) dis = rsqrt(deg)   (deg >= 1 always, no zero guard needed)
__global__ void k_dis(int n_nodes) {
    int i = blockIdx.x * blockDim.x + threadIdx.x;
    if (i < n_nodes) g_dis[i] = rsqrtf(g_deg[i]);
}

// 4) h = x @ K.  Register-tiled: block = 256 thr, 32-row tile.
//    Thread (r = tid>>3, c4 = tid&7) computes row r, cols [c4*8, c4*8+8).
//    Per k-step: 1 smem x broadcast + 2 float4 K loads -> 8 FFMA.
__global__ void __launch_bounds__(256) k_gemm(const float4* __restrict__ x4,
                                              const float4* __restrict__ K4,
                                              int n_nodes) {
    __shared__ float4 sK4[D * 16];        // K: 64 rows x 16 float4 = 16 KB
    __shared__ float4 sX4[GR * 17];       // x tile: 32 rows x 16 float4 + pad
    int tid  = threadIdx.x;
    int row0 = blockIdx.x * GR;

    // stage K (1024 float4)
    for (int i = tid; i < D * 16; i += 256) sK4[i] = K4[i];
    // stage x tile (512 float4), coalesced
    for (int i = tid; i < GR * 16; i += 256) {
        int r = i >> 4, c = i & 15;
        int gr = row0 + r;
        if (gr < n_nodes) sX4[r * 17 + c] = x4[gr * 16 + c];
    }
    __syncthreads();

    int r  = tid >> 3;          // 0..31
    int c4 = tid & 7;           // 0..7  -> float4 cols c4*2, c4*2+1
    const float* sx = reinterpret_cast<const float*>(sX4 + r * 17);

    float4 a0 = make_float4(0.f, 0.f, 0.f, 0.f);
    float4 a1 = make_float4(0.f, 0.f, 0.f, 0.f);
#pragma unroll
    for (int k = 0; k < D; k++) {
        float  xv = sx[k];
        float4 k0 = sK4[k * 16 + c4 * 2];
        float4 k1 = sK4[k * 16 + c4 * 2 + 1];
        a0.x += xv * k0.x; a0.y += xv * k0.y; a0.z += xv * k0.z; a0.w += xv * k0.w;
        a1.x += xv * k1.x; a1.y += xv * k1.y; a1.z += xv * k1.z; a1.w += xv * k1.w;
    }
    int gr = row0 + r;
    if (gr < n_nodes) {
        g_h[gr * 16 + c4 * 2]     = a0;
        g_h[gr * 16 + c4 * 2 + 1] = a1;
    }
}

// 5) h[id_index[t]] += x[id_index[t]] @ K_id  (atomic: id_index may repeat)
__global__ void k_gemm_id(const float* __restrict__ x,
                          const float* __restrict__ Kid,
                          const int* __restrict__ id_index, int n_id) {
    __shared__ float sK[D][D];
    int tid = threadIdx.x;
    for (int i = tid; i < D * D; i += 256) sK[i >> 6][i & 63] = Kid[i];
    __syncthreads();
    int r = tid >> 6;
    int j = tid & 63;
    int t = blockIdx.x * 4 + r;
    if (t < n_id) {
        int node = __ldg(&id_index[t]);
        const float* xr = x + node * D;
        float acc = 0.0f;
#pragma unroll
        for (int k = 0; k < D; k++) acc += __ldg(&xr[k]) * sK[k][j];
        atomicAdd(&reinterpret_cast<float*>(g_h)[node * D + j], acc);
    }
}

// 6) out init: bias + self-loop contribution  out[i] = bias + dis[i]^2 * h[i]
__global__ void k_out_init(float4* __restrict__ out,
                           const float* __restrict__ bias, int n_nodes) {
    int t = blockIdx.x * blockDim.x + threadIdx.x;
    if (t < n_nodes * D4) {
        int node = t >> 4;
        int l    = t & 15;
        float s  = g_dis[node];
        s = s * s;
        float4 hv = g_h[t];
        float4 b  = reinterpret_cast<const float4*>(bias)[l];
        out[t] = make_float4(b.x + s * hv.x, b.y + s * hv.y,
                             b.z + s * hv.z, b.w + s * hv.w);
    }
}

// 7) SpMM: 16 lanes per edge, float4 gather + float4 vector atomicAdd
__global__ void __launch_bounds__(256) k_spmm(const int* __restrict__ row,
                       const int* __restrict__ col,
                       const float* __restrict__ w,
                       float4* __restrict__ out, int n_edges) {
    int t = blockIdx.x * blockDim.x + threadIdx.x;
    int e = t >> 4;
    int l = t & 15;
    if (e < n_edges) {
        int r = __ldg(&row[e]);
        int c = __ldg(&col[e]);
        float wn = __ldg(&g_dis[r]) * __ldg(&w[e]) * __ldg(&g_dis[c]);
        float4 v = g_h[c * D4 + l];
        v.x *= wn; v.y *= wn; v.z *= wn; v.w *= wn;
        atom_add_f4(&out[r * D4 + l], v);
    }
}

extern "C" void kernel_launch(void* const* d_in, const int* in_sizes, int n_in,
                              void* d_out, int out_size) {
    const float* x        = (const float*)d_in[0];
    const int*   ei       = (const int*)d_in[1];
    const int*   id_index = (const int*)d_in[2];
    const float* ew       = (const float*)d_in[3];
    const float* K        = (const float*)d_in[4];
    const float* Kid      = (const float*)d_in[5];
    const float* bias     = (const float*)d_in[6];
    float*       out      = (float*)d_out;

    int n_nodes = in_sizes[0] / D;
    int n_edges = in_sizes[1] / 2;
    int n_id    = in_sizes[2];

    const int* row  = ei;
    const int* colp = ei + n_edges;

    k_deg_init<<<(n_nodes + 255) / 256, 256>>>(n_nodes);
    k_deg_acc<<<(n_edges + 255) / 256, 256>>>(row, ew, n_edges);
    k_dis<<<(n_nodes + 255) / 256, 256>>>(n_nodes);
    k_gemm<<<(n_nodes + GR - 1) / GR, 256>>>((const float4*)x,
                                             (const float4*)K, n_nodes);
    k_gemm_id<<<(n_id + 3) / 4, 256>>>(x, Kid, id_index, n_id);
    k_out_init<<<(n_nodes * D4 + 255) / 256, 256>>>((float4*)out, bias, n_nodes);
    k_spmm<<<((long long)n_edges * 16 + 255) / 256, 256>>>(row, colp, ew,
                                                           (float4*)out, n_edges);
}

// round 6
// speedup vs baseline: 1.6465x; 1.4756x over previous
#include <cuda_runtime.h>
#include <cuda_bf16.h>

#define D 64
#define D4 (D / 4)          // 16 float4 per row
#define NODES_MAX 100000
#define GR 64               // gemm rows per block (smem: 16KB K + 16KB x = 32KB)

// Scratch (static device globals: allocation-free, allowed by harness rules)
__device__ float  g_deg[NODES_MAX];
__device__ float  g_dis[NODES_MAX];
__device__ float4 g_h[NODES_MAX * D4];   // h = x@K (+ id contribution), 25.6 MB

// Vector atomic add with scalar fallback
__device__ __forceinline__ void atom_add_f4(float4* addr, float4 v) {
#if defined(__CUDA_ARCH__) && (__CUDA_ARCH__ >= 900)
    atomicAdd(addr, v);
#else
    float* p = reinterpret_cast<float*>(addr);
    atomicAdd(p + 0, v.x);
    atomicAdd(p + 1, v.y);
    atomicAdd(p + 2, v.z);
    atomicAdd(p + 3, v.w);
#endif
}

__device__ __forceinline__ void fma4(float4& a, float s, const float4& k) {
    a.x += s * k.x; a.y += s * k.y; a.z += s * k.z; a.w += s * k.w;
}

// ---------------------------------------------------------------------------
// 1) deg init: self-loop weight 1.0
__global__ void k_deg_init(int n_nodes) {
    int i = blockIdx.x * blockDim.x + threadIdx.x;
    if (i < n_nodes) g_deg[i] = 1.0f;
}

// 2) deg accumulate over edges (segment_sum by row)
__global__ void __launch_bounds__(256) k_deg_acc(const int* __restrict__ row,
                          const float* __restrict__ w, int n_edges) {
    int e = blockIdx.x * blockDim.x + threadIdx.x;
    if (e < n_edges) atomicAdd(&g_deg[row[e]], w[e]);
}

// 3) dis = rsqrt(deg)   (deg >= 1 always, no zero guard needed)
__global__ void k_dis(int n_nodes) {
    int i = blockIdx.x * blockDim.x + threadIdx.x;
    if (i < n_nodes) g_dis[i] = rsqrtf(g_deg[i]);
}

// 4) h = x @ K.  Block: 256 thr -> 64-row x 64-col tile, 32KB static smem.
//    Thread (rg = tid>>4, cg = tid&15) computes rows rg*4..+3, float4-col cg.
//    Per 4-k chunk: 4 broadcast x-LDS.128 + 4 K-LDS.128 feed 64 FFMAs.
__global__ void __launch_bounds__(256) k_gemm(const float4* __restrict__ x4,
                                              const float4* __restrict__ K4,
                                              int n_nodes) {
    __shared__ float4 sK4[D * 16];        // K: 64 rows x 16 float4 = 16 KB
    __shared__ float4 sX4[GR * 16];       // x tile: 64 rows x 16 float4 = 16 KB
    int tid  = threadIdx.x;
    int row0 = blockIdx.x * GR;

    // stage K (1024 float4)
    for (int i = tid; i < D * 16; i += 256) sK4[i] = K4[i];
    // stage x tile (1024 float4), coalesced; zero-pad ragged tail
    {
        int i = tid;                       // exactly 4 iterations of 256
#pragma unroll
        for (int it = 0; it < 4; it++, i += 256) {
            int gr = row0 + (i >> 4);
            sX4[i] = (gr < n_nodes) ? x4[gr * 16 + (i & 15)]
                                    : make_float4(0.f, 0.f, 0.f, 0.f);
        }
    }
    __syncthreads();

    int rg = tid >> 4;          // 0..15 -> 4-row group
    int cg = tid & 15;          // 0..15 -> float4 column

    float4 acc[4];
#pragma unroll
    for (int i = 0; i < 4; i++) acc[i] = make_float4(0.f, 0.f, 0.f, 0.f);

#pragma unroll
    for (int kc = 0; kc < 16; kc++) {     // 4 k-values per chunk
        float4 xv[4];
#pragma unroll
        for (int i = 0; i < 4; i++) xv[i] = sX4[(rg * 4 + i) * 16 + kc];

#pragma unroll
        for (int kk = 0; kk < 4; kk++) {
            float4 kv = sK4[(kc * 4 + kk) * 16 + cg];
#pragma unroll
            for (int i = 0; i < 4; i++) {
                float s = reinterpret_cast<const float*>(&xv[i])[kk];
                fma4(acc[i], s, kv);
            }
        }
    }

#pragma unroll
    for (int i = 0; i < 4; i++) {
        int gr = row0 + rg * 4 + i;
        if (gr < n_nodes) g_h[gr * 16 + cg] = acc[i];
    }
}

// 5) h[id_index[t]] += x[id_index[t]] @ K_id  (atomic: id_index may repeat)
__global__ void k_gemm_id(const float* __restrict__ x,
                          const float* __restrict__ Kid,
                          const int* __restrict__ id_index, int n_id) {
    __shared__ float sK[D][D];
    int tid = threadIdx.x;
    for (int i = tid; i < D * D; i += 256) sK[i >> 6][i & 63] = Kid[i];
    __syncthreads();
    int r = tid >> 6;
    int j = tid & 63;
    int t = blockIdx.x * 4 + r;
    if (t < n_id) {
        int node = __ldg(&id_index[t]);
        const float* xr = x + node * D;
        float acc = 0.0f;
#pragma unroll
        for (int k = 0; k < D; k++) acc += __ldg(&xr[k]) * sK[k][j];
        atomicAdd(&reinterpret_cast<float*>(g_h)[node * D + j], acc);
    }
}

// 6) out init: bias + self-loop contribution  out[i] = bias + dis[i]^2 * h[i]
__global__ void k_out_init(float4* __restrict__ out,
                           const float* __restrict__ bias, int n_nodes) {
    int t = blockIdx.x * blockDim.x + threadIdx.x;
    if (t < n_nodes * D4) {
        int node = t >> 4;
        int l    = t & 15;
        float s  = g_dis[node];
        s = s * s;
        float4 hv = g_h[t];
        float4 b  = reinterpret_cast<const float4*>(bias)[l];
        out[t] = make_float4(b.x + s * hv.x, b.y + s * hv.y,
                             b.z + s * hv.z, b.w + s * hv.w);
    }
}

// 7) SpMM: 16 lanes per edge, float4 gather + float4 vector atomicAdd
__global__ void __launch_bounds__(256) k_spmm(const int* __restrict__ row,
                       const int* __restrict__ col,
                       const float* __restrict__ w,
                       float4* __restrict__ out, int n_edges) {
    int t = blockIdx.x * blockDim.x + threadIdx.x;
    int e = t >> 4;
    int l = t & 15;
    if (e < n_edges) {
        int r = __ldg(&row[e]);
        int c = __ldg(&col[e]);
        float wn = __ldg(&g_dis[r]) * __ldg(&w[e]) * __ldg(&g_dis[c]);
        float4 v = g_h[c * D4 + l];
        v.x *= wn; v.y *= wn; v.z *= wn; v.w *= wn;
        atom_add_f4(&out[r * D4 + l], v);
    }
}

extern "C" void kernel_launch(void* const* d_in, const int* in_sizes, int n_in,
                              void* d_out, int out_size) {
    const float* x        = (const float*)d_in[0];
    const int*   ei       = (const int*)d_in[1];
    const int*   id_index = (const int*)d_in[2];
    const float* ew       = (const float*)d_in[3];
    const float* K        = (const float*)d_in[4];
    const float* Kid      = (const float*)d_in[5];
    const float* bias     = (const float*)d_in[6];
    float*       out      = (float*)d_out;

    int n_nodes = in_sizes[0] / D;
    int n_edges = in_sizes[1] / 2;
    int n_id    = in_sizes[2];

    const int* row  = ei;
    const int* colp = ei + n_edges;

    k_deg_init<<<(n_nodes + 255) / 256, 256>>>(n_nodes);
    k_deg_acc<<<(n_edges + 255) / 256, 256>>>(row, ew, n_edges);
    k_dis<<<(n_nodes + 255) / 256, 256>>>(n_nodes);
    k_gemm<<<(n_nodes + GR - 1) / GR, 256>>>((const float4*)x,
                                             (const float4*)K, n_nodes);
    k_gemm_id<<<(n_id + 3) / 4, 256>>>(x, Kid, id_index, n_id);
    k_out_init<<<(n_nodes * D4 + 255) / 256, 256>>>((float4*)out, bias, n_nodes);
    k_spmm<<<((long long)n_edges * 16 + 255) / 256, 256>>>(row, colp, ew,
                                                           (float4*)out, n_edges);
}

// round 7
// speedup vs baseline: 1.8017x; 1.0942x over previous
#include <cuda_runtime.h>
#include <cuda_bf16.h>

#define D 64
#define D4 (D / 4)          // 16 float4 per row
#define NODES_MAX 100000
#define EDGES_MAX 1600000
#define GR 64               // gemm rows per block (smem: 16KB K + 16KB x = 32KB)
#define NB_MAX 512          // max scan blocks (supports up to 131072 nodes)

// Scratch (static device globals: allocation-free, allowed by harness rules)
__device__ float  g_deg[NODES_MAX];
__device__ float  g_dis[NODES_MAX];
__device__ int    g_cnt[NODES_MAX];       // edges per row
__device__ int    g_rowstart[NODES_MAX];  // CSR offsets (exclusive scan of cnt)
__device__ int    g_cursor[NODES_MAX];    // scatter cursors
__device__ int    g_bsum[NB_MAX];
__device__ int    g_boff[NB_MAX];
__device__ float2 g_ecw[EDGES_MAX];       // CSR payload: (col bits, wn)
__device__ float4 g_h[NODES_MAX * D4];    // h = x@K (+ id contribution)

__device__ __forceinline__ void fma4(float4& a, float s, const float4& k) {
    a.x += s * k.x; a.y += s * k.y; a.z += s * k.z; a.w += s * k.w;
}

// ---------------------------------------------------------------------------
// 1) init: deg = 1 (self loop), cnt = 0
__global__ void k_deg_init(int n_nodes) {
    int i = blockIdx.x * blockDim.x + threadIdx.x;
    if (i < n_nodes) { g_deg[i] = 1.0f; g_cnt[i] = 0; }
}

// 2) deg accumulate + per-row edge histogram
__global__ void __launch_bounds__(256) k_deg_acc(const int* __restrict__ row,
                          const float* __restrict__ w, int n_edges) {
    int e = blockIdx.x * blockDim.x + threadIdx.x;
    if (e < n_edges) {
        int r = row[e];
        atomicAdd(&g_deg[r], w[e]);
        atomicAdd(&g_cnt[r], 1);
    }
}

// 3) dis = rsqrt(deg)   (deg >= 1 always)
__global__ void k_dis(int n_nodes) {
    int i = blockIdx.x * blockDim.x + threadIdx.x;
    if (i < n_nodes) g_dis[i] = rsqrtf(g_deg[i]);
}

// 4a) scan pass 1: per-block (256) sums of cnt
__global__ void k_scan1(int n_nodes) {
    __shared__ int sh[256];
    int t = threadIdx.x;
    int i = blockIdx.x * 256 + t;
    sh[t] = (i < n_nodes) ? g_cnt[i] : 0;
    __syncthreads();
    for (int o = 128; o > 0; o >>= 1) {
        if (t < o) sh[t] += sh[t + o];
        __syncthreads();
    }
    if (t == 0) g_bsum[blockIdx.x] = sh[0];
}

// 4b) scan pass 2: exclusive scan of block sums (single block, 512 thr)
__global__ void k_scan2(int nb) {
    __shared__ int sh[NB_MAX];
    int t = threadIdx.x;
    int v = (t < nb) ? g_bsum[t] : 0;
    sh[t] = v;
    __syncthreads();
    for (int o = 1; o < NB_MAX; o <<= 1) {
        int a = (t >= o) ? sh[t - o] : 0;
        __syncthreads();
        sh[t] += a;
        __syncthreads();
    }
    g_boff[t] = sh[t] - v;   // exclusive
}

// 4c) scan pass 3: per-block exclusive scan + block offset -> rowstart, cursor
__global__ void k_scan3(int n_nodes) {
    __shared__ int sh[256];
    int t = threadIdx.x;
    int i = blockIdx.x * 256 + t;
    int v = (i < n_nodes) ? g_cnt[i] : 0;
    sh[t] = v;
    __syncthreads();
    for (int o = 1; o < 256; o <<= 1) {
        int a = (t >= o) ? sh[t - o] : 0;
        __syncthreads();
        sh[t] += a;
        __syncthreads();
    }
    int excl = sh[t] - v + g_boff[blockIdx.x];
    if (i < n_nodes) { g_rowstart[i] = excl; g_cursor[i] = excl; }
}

// 5) scatter edges into CSR slots with precomputed normalized weight
__global__ void __launch_bounds__(256) k_scatter(const int* __restrict__ row,
                      const int* __restrict__ col,
                      const float* __restrict__ w, int n_edges) {
    int e = blockIdx.x * blockDim.x + threadIdx.x;
    if (e < n_edges) {
        int r = __ldg(&row[e]);
        int c = __ldg(&col[e]);
        float wn = g_dis[r] * __ldg(&w[e]) * g_dis[c];
        int pos = atomicAdd(&g_cursor[r], 1);
        g_ecw[pos] = make_float2(__int_as_float(c), wn);
    }
}

// 6) h = x @ K.  Block: 256 thr -> 64x64 tile, 32KB static smem. (R6 kernel)
__global__ void __launch_bounds__(256) k_gemm(const float4* __restrict__ x4,
                                              const float4* __restrict__ K4,
                                              int n_nodes) {
    __shared__ float4 sK4[D * 16];
    __shared__ float4 sX4[GR * 16];
    int tid  = threadIdx.x;
    int row0 = blockIdx.x * GR;

    for (int i = tid; i < D * 16; i += 256) sK4[i] = K4[i];
    {
        int i = tid;
#pragma unroll
        for (int it = 0; it < 4; it++, i += 256) {
            int gr = row0 + (i >> 4);
            sX4[i] = (gr < n_nodes) ? x4[gr * 16 + (i & 15)]
                                    : make_float4(0.f, 0.f, 0.f, 0.f);
        }
    }
    __syncthreads();

    int rg = tid >> 4;
    int cg = tid & 15;

    float4 acc[4];
#pragma unroll
    for (int i = 0; i < 4; i++) acc[i] = make_float4(0.f, 0.f, 0.f, 0.f);

#pragma unroll
    for (int kc = 0; kc < 16; kc++) {
        float4 xv[4];
#pragma unroll
        for (int i = 0; i < 4; i++) xv[i] = sX4[(rg * 4 + i) * 16 + kc];
#pragma unroll
        for (int kk = 0; kk < 4; kk++) {
            float4 kv = sK4[(kc * 4 + kk) * 16 + cg];
#pragma unroll
            for (int i = 0; i < 4; i++) {
                float s = reinterpret_cast<const float*>(&xv[i])[kk];
                fma4(acc[i], s, kv);
            }
        }
    }

#pragma unroll
    for (int i = 0; i < 4; i++) {
        int gr = row0 + rg * 4 + i;
        if (gr < n_nodes) g_h[gr * 16 + cg] = acc[i];
    }
}

// 7) h[id_index[t]] += x[id_index[t]] @ K_id  (atomic: id_index may repeat)
__global__ void k_gemm_id(const float* __restrict__ x,
                          const float* __restrict__ Kid,
                          const int* __restrict__ id_index, int n_id) {
    __shared__ float sK[D][D];
    int tid = threadIdx.x;
    for (int i = tid; i < D * D; i += 256) sK[i >> 6][i & 63] = Kid[i];
    __syncthreads();
    int r = tid >> 6;
    int j = tid & 63;
    int t = blockIdx.x * 4 + r;
    if (t < n_id) {
        int node = __ldg(&id_index[t]);
        const float* xr = x + node * D;
        float acc = 0.0f;
#pragma unroll
        for (int k = 0; k < D; k++) acc += __ldg(&xr[k]) * sK[k][j];
        atomicAdd(&reinterpret_cast<float*>(g_h)[node * D + j], acc);
    }
}

// 8) CSR SpMM: one warp per row; halfwarves process 2 edges/iter.
//    out[r] = bias + dis[r]^2 * h[r] + sum_e wn[e] * h[col[e]]   (no atomics)
__global__ void __launch_bounds__(256) k_spmm_csr(const float4* __restrict__ bias4,
                       float4* __restrict__ out, int n_nodes) {
    int r    = (blockIdx.x * blockDim.x + threadIdx.x) >> 5;
    int lane = threadIdx.x & 31;
    if (r >= n_nodes) return;
    int base = g_rowstart[r];
    int deg  = g_cnt[r];
    int half = lane >> 4;     // 0: even edges, 1: odd edges
    int l    = lane & 15;     // float4 column

    float4 acc = make_float4(0.f, 0.f, 0.f, 0.f);
    for (int i = half; i < deg; i += 2) {
        float2 ew = __ldg(&g_ecw[base + i]);
        int    c  = __float_as_int(ew.x);
        float4 hv = g_h[c * 16 + l];
        fma4(acc, ew.y, hv);
    }
    // combine odd-half into even-half
    acc.x += __shfl_down_sync(0xffffffffu, acc.x, 16);
    acc.y += __shfl_down_sync(0xffffffffu, acc.y, 16);
    acc.z += __shfl_down_sync(0xffffffffu, acc.z, 16);
    acc.w += __shfl_down_sync(0xffffffffu, acc.w, 16);

    if (half == 0) {
        float s = g_dis[r];
        s = s * s;
        float4 hv = g_h[r * 16 + l];
        float4 b  = __ldg(&bias4[l]);
        out[r * 16 + l] = make_float4(b.x + s * hv.x + acc.x,
                                      b.y + s * hv.y + acc.y,
                                      b.z + s * hv.z + acc.z,
                                      b.w + s * hv.w + acc.w);
    }
}

extern "C" void kernel_launch(void* const* d_in, const int* in_sizes, int n_in,
                              void* d_out, int out_size) {
    const float* x        = (const float*)d_in[0];
    const int*   ei       = (const int*)d_in[1];
    const int*   id_index = (const int*)d_in[2];
    const float* ew       = (const float*)d_in[3];
    const float* K        = (const float*)d_in[4];
    const float* Kid      = (const float*)d_in[5];
    const float* bias     = (const float*)d_in[6];
    float*       out      = (float*)d_out;

    int n_nodes = in_sizes[0] / D;
    int n_edges = in_sizes[1] / 2;
    int n_id    = in_sizes[2];
    int nb      = (n_nodes + 255) / 256;

    const int* row  = ei;
    const int* colp = ei + n_edges;

    k_deg_init<<<nb, 256>>>(n_nodes);
    k_deg_acc<<<(n_edges + 255) / 256, 256>>>(row, ew, n_edges);
    k_dis<<<nb, 256>>>(n_nodes);
    k_scan1<<<nb, 256>>>(n_nodes);
    k_scan2<<<1, NB_MAX>>>(nb);
    k_scan3<<<nb, 256>>>(n_nodes);
    k_scatter<<<(n_edges + 255) / 256, 256>>>(row, colp, ew, n_edges);
    k_gemm<<<(n_nodes + GR - 1) / GR, 256>>>((const float4*)x,
                                             (const float4*)K, n_nodes);
    k_gemm_id<<<(n_id + 3) / 4, 256>>>(x, Kid, id_index, n_id);
    k_spmm_csr<<<(n_nodes * 32 + 255) / 256, 256>>>((const float4*)bias,
                                                    (float4*)out, n_nodes);
}